// round 13
// baseline (speedup 1.0000x reference)
#include <cuda_runtime.h>
#include <math.h>
#include <stddef.h>

// Problem dims
#define TT 512
#define BB 64
#define II 256
#define HH 512
#define OO 256
#define G4 (4*HH)
#define NBLK 128
// 8 groups x 8 batches; block = 2 anti-phase subunits (groups 2p, 2p+1)
#define NGRP 8
#define UPG  32          // units per group (one per col-block)
#define BATG 8           // batches per group
#define NTHR 512

// ---------------- device scratch ----------------
__device__ float g_xp1[(size_t)TT*BB*G4];
__device__ float g_xp2[(size_t)BB*G4];
__device__ float g_hP[2][(size_t)BB*HH];    // ping-pong h, batch-major [b][col]
__device__ float g_hA[(size_t)BB*HH];       // layer-1 final h
__device__ float g_hs2[(size_t)TT*BB*HH];
__device__ unsigned g_flags[NGRP*UPG];      // per-unit monotonic step counters

// ---------------- helpers ----------------
typedef unsigned long long u64t;

__device__ __forceinline__ void fma2(u64t& acc, u64t a, u64t b) {
    asm volatile("fma.rn.f32x2 %0, %1, %2, %0;" : "+l"(acc) : "l"(a), "l"(b));
}
__device__ __forceinline__ u64t pk2(float x, float y) {
    u64t r; asm("mov.b64 %0, {%1, %2};" : "=l"(r) : "f"(x), "f"(y)); return r;
}
__device__ __forceinline__ float2 unpk2(u64t v) {
    float2 f; asm("mov.b64 {%0, %1}, %2;" : "=f"(f.x), "=f"(f.y) : "l"(v)); return f;
}
__device__ __forceinline__ void cp_async16(void* dst_smem, const void* src_gmem) {
    unsigned d = (unsigned)__cvta_generic_to_shared(dst_smem);
    asm volatile("cp.async.cg.shared.global [%0], [%1], 16;" :: "r"(d), "l"(src_gmem) : "memory");
}
__device__ __forceinline__ void st_release(unsigned* p, unsigned v) {
    asm volatile("st.global.release.gpu.u32 [%0], %1;" :: "l"(p), "r"(v) : "memory");
}
__device__ __forceinline__ unsigned ld_acquire(const unsigned* p) {
    unsigned r;
    asm volatile("ld.global.acquire.gpu.u32 %0, [%1];" : "=r"(r) : "l"(p) : "memory");
    return r;
}
__device__ __forceinline__ void bar_named(int id) {
    asm volatile("bar.sync %0, 256;" :: "r"(id) : "memory");
}
__device__ __forceinline__ float fsig(float x)  { return __fdividef(1.f, 1.f + __expf(-x)); }
__device__ __forceinline__ float ftanh(float x) { return __fdividef(2.f, 1.f + __expf(-2.f*x)) - 1.f; }

// =================================================================================
// SGEMM with f32x2 (unchanged, passing)
// =================================================================================
__global__ __launch_bounds__(256) void gemm_bias_kernel(
    const float* __restrict__ A, const float* __restrict__ B,
    const float* __restrict__ bias1, const float* __restrict__ bias2,
    float* __restrict__ C, int M, int N, int K)
{
    __shared__ float As[8][128];
    __shared__ float Bs[8][128];

    const int tid  = threadIdx.x;
    const int row0 = blockIdx.y * 128;
    const int col0 = blockIdx.x * 128;

    const int lrow = tid >> 1;
    const int lcol = (tid & 1) << 2;
    const int tr   = (tid >> 4) << 3;
    const int tc   = (tid & 15) << 3;

    u64t acc2[4][8];
    #pragma unroll
    for (int i = 0; i < 4; i++)
        #pragma unroll
        for (int j = 0; j < 8; j++) acc2[i][j] = 0ull;

    for (int k0 = 0; k0 < K; k0 += 8) {
        float4 av = make_float4(0.f, 0.f, 0.f, 0.f);
        if (row0 + lrow < M)
            av = *(const float4*)(A + (size_t)(row0 + lrow) * K + k0 + lcol);
        As[lcol+0][lrow] = av.x;
        As[lcol+1][lrow] = av.y;
        As[lcol+2][lrow] = av.z;
        As[lcol+3][lrow] = av.w;

        float4 bv = *(const float4*)(B + (size_t)(col0 + lrow) * K + k0 + lcol);
        Bs[lcol+0][lrow] = bv.x;
        Bs[lcol+1][lrow] = bv.y;
        Bs[lcol+2][lrow] = bv.z;
        Bs[lcol+3][lrow] = bv.w;

        __syncthreads();

        #pragma unroll
        for (int kk = 0; kk < 8; kk++) {
            ulonglong2 raA = *(const ulonglong2*)&As[kk][tr];
            ulonglong2 raB = *(const ulonglong2*)&As[kk][tr + 4];
            float rb[8];
            *(float4*)(rb)     = *(const float4*)&Bs[kk][tc];
            *(float4*)(rb + 4) = *(const float4*)&Bs[kk][tc + 4];
            u64t rbd[8];
            #pragma unroll
            for (int j = 0; j < 8; j++) rbd[j] = pk2(rb[j], rb[j]);
            #pragma unroll
            for (int j = 0; j < 8; j++) {
                fma2(acc2[0][j], raA.x, rbd[j]);
                fma2(acc2[1][j], raA.y, rbd[j]);
                fma2(acc2[2][j], raB.x, rbd[j]);
                fma2(acc2[3][j], raB.y, rbd[j]);
            }
        }
        __syncthreads();
    }

    float bsum[8];
    #pragma unroll
    for (int j = 0; j < 8; j++) {
        float b = bias1 ? bias1[col0 + tc + j] : 0.f;
        if (bias2) b += bias2[col0 + tc + j];
        bsum[j] = b;
    }

    #pragma unroll
    for (int i2 = 0; i2 < 4; i2++) {
        #pragma unroll
        for (int half = 0; half < 2; half++) {
            int r = row0 + tr + i2 * 2 + half;
            if (r < M) {
                #pragma unroll
                for (int j = 0; j < 8; j += 4) {
                    float4 o;
                    float2 u0 = unpk2(acc2[i2][j+0]);
                    float2 u1 = unpk2(acc2[i2][j+1]);
                    float2 u2 = unpk2(acc2[i2][j+2]);
                    float2 u3 = unpk2(acc2[i2][j+3]);
                    o.x = (half ? u0.y : u0.x) + bsum[j+0];
                    o.y = (half ? u1.y : u1.x) + bsum[j+1];
                    o.z = (half ? u2.y : u2.x) + bsum[j+2];
                    o.w = (half ? u3.y : u3.x) + bsum[j+3];
                    *(float4*)(C + (size_t)r * N + col0 + tc + j) = o;
                }
            }
        }
    }
}

// =================================================================================
// Per-warp-dataflow anti-phase persistent LSTM.
// Block b: cols [16*(b&31), +16) (64 gate rows); pair p=b>>5; subunit hh=tid>>8
// handles group 2p+hh (batches [8g, 8g+8)). Shared W 128KB.
//
// Warp kw (0..7) of a subunit owns k-slice [64kw, 64kw+64) = producer units
// {4kw..4kw+3}. Per step, the warp ALONE: polls its 4 flags -> cp.asyncs its 2KB
// h slice -> computes its k-slice. Warps decouple until the partials bar, so
// producer skew hides under compute. Only 2 block-half bars per step.
// Lane: rg=lane>>2 (cols rg, rg+8), bq=lane&3 (batches 2bq, 2bq+1).
// Tail: lanes 0-15 of every warp; cell = (batch=kw, col=lane).
// =================================================================================
#define WS4F  (64*128)                   // W float4 (128KB)
#define HS4F  (8*128)                    // h float4 per subunit: 8 warps x 128 (16KB)
#define REDST 9                          // red stride (float4) per col, padded
#define RED4F (8*16*REDST)               // red float4 per subunit (18KB)
#define STEP_SMEM_BYTES ((WS4F + 2*HS4F + 2*RED4F) * 16)   // 200,704 B

__global__ __launch_bounds__(NTHR, 1) void lstm_persist_kernel(
    const float* __restrict__ h0, const float* __restrict__ c0,
    float* __restrict__ h_final,
    const float* __restrict__ W, const float* __restrict__ xp,
    long long xp_t_stride, float* __restrict__ hs_out)
{
    extern __shared__ float smem[];
    float4* smem4 = (float4*)smem;
    __shared__ unsigned s_base[2];

    const int tid  = threadIdx.x;
    const int hh   = tid >> 8;            // subunit 0/1
    const int lt   = tid & 255;           // thread within subunit
    const int lane = tid & 31;
    const int kw   = lt >> 5;             // warp in subunit = k-slice 0..7
    const int rg   = lane >> 2;           // col selector (cols rg, rg+8)
    const int bq   = lane & 3;            // batch pair selector (2bq, 2bq+1)
    const int p    = blockIdx.x >> 5;
    const int cb8  = blockIdx.x & 31;
    const int group = 2 * p + hh;
    const int jj0  = cb8 * 16;
    const int bq0  = group * BATG;
    const int fidx = group * UPG + cb8;
    const int barid = 1 + hh;

    float4* wS   = smem4;                               // [64 r][128 k4], swz k4^(col&7)
    float4* hS   = smem4 + WS4F + hh * HS4F;            // [kw][b][16 k4], swz k4l^(b&7)
    float4* redB = smem4 + WS4F + 2*HS4F + hh * RED4F;  // [8 kw][16 col][9]

    // ---- stage shared W once: row r = col*4 + gate ----
    for (int idx = tid; idx < WS4F; idx += NTHR) {
        int r = idx >> 7, k4 = idx & 127;
        int col = r >> 2, g = r & 3;
        wS[r * 128 + (k4 ^ (col & 7))] =
            ((const float4*)(W + (size_t)(g * HH + jj0 + col) * HH))[k4];
    }

    // ---- tail cell state: lanes 0-15 of each warp: (batch=kw, col=lane) ----
    const int bglob = bq0 + kw;
    const int jglob = jj0 + lane;         // valid for lane < 16
    float creg = 0.f;
    if (lane < 16) creg = c0[(size_t)bglob * HH + jglob];

    if (lt == 0) s_base[hh] = g_flags[fidx];
    __syncthreads();                      // only block-wide sync
    const unsigned base = s_base[hh];

    float4* hW = hS + kw * 128;           // this warp's slice [8 b][16 k4]

    for (int t = 0; t < TT; t++) {
        // ---- xp prefetch (lanes<16; consumed in tail) ----
        float xi = 0.f, xf = 0.f, xg = 0.f, xo = 0.f;
        if (lane < 16) {
            const float* xt = xp + (size_t)(xp_t_stride * t) + (size_t)bglob * G4 + jglob;
            xi = xt[0*HH];
            xf = xt[1*HH];
            xg = xt[2*HH];
            xo = xt[3*HH];
        }

        // ---- per-warp: poll own 4 producers, then stage own 2KB slice ----
        const float* hsrc = (t == 0) ? h0 : g_hP[(t + 1) & 1];
        if (t > 0) {
            const unsigned target = base + (unsigned)t;
            const unsigned* fb = &g_flags[group * UPG + 4 * kw];
            for (;;) {
                unsigned f0 = ld_acquire(fb + 0);
                unsigned f1 = ld_acquire(fb + 1);
                unsigned f2 = ld_acquire(fb + 2);
                unsigned f3 = ld_acquire(fb + 3);
                if ((int)(f0 - target) >= 0 && (int)(f1 - target) >= 0 &&
                    (int)(f2 - target) >= 0 && (int)(f3 - target) >= 0) break;
            }
            __syncwarp();
        }
        #pragma unroll
        for (int q = 0; q < 4; q++) {
            int idx = lane * 4 + q;       // 0..127
            int b   = idx >> 4;
            int k4l = idx & 15;
            cp_async16(hW + b * 16 + (k4l ^ (b & 7)),
                       (const float4*)hsrc + (size_t)(bq0 + b) * 128 + kw * 16 + k4l);
        }
        asm volatile("cp.async.commit_group;" ::: "memory");
        asm volatile("cp.async.wait_group 0;" ::: "memory");
        __syncwarp();

        // ---- compute own k-slice: cols {rg, rg+8} x 4 gates x 2 batches x 64 k ----
        u64t acc2[2][4][2];
        #pragma unroll
        for (int cc = 0; cc < 2; cc++)
            #pragma unroll
            for (int g = 0; g < 4; g++)
                #pragma unroll
                for (int i = 0; i < 2; i++) acc2[cc][g][i] = 0ull;

        #pragma unroll 8
        for (int it = 0; it < 16; it++) {
            int k4g = kw * 16 + it;
            ulonglong2 wv[2][4];
            #pragma unroll
            for (int cc = 0; cc < 2; cc++)
                #pragma unroll
                for (int g = 0; g < 4; g++) {
                    int row = (rg + 8 * cc) * 4 + g;
                    wv[cc][g] = *(const ulonglong2*)(wS + row * 128 + (k4g ^ rg));
                }
            ulonglong2 hv[2];
            #pragma unroll
            for (int i = 0; i < 2; i++) {
                int b = bq * 2 + i;
                hv[i] = *(const ulonglong2*)(hW + b * 16 + (it ^ (b & 7)));
            }
            #pragma unroll
            for (int cc = 0; cc < 2; cc++)
                #pragma unroll
                for (int g = 0; g < 4; g++)
                    #pragma unroll
                    for (int i = 0; i < 2; i++) {
                        fma2(acc2[cc][g][i], hv[i].x, wv[cc][g].x);
                        fma2(acc2[cc][g][i], hv[i].y, wv[cc][g].y);
                    }
        }

        // ---- partials: redB[kw][col][batch] (stride 9), float4 over gates ----
        #pragma unroll
        for (int cc = 0; cc < 2; cc++)
            #pragma unroll
            for (int i = 0; i < 2; i++) {
                int jzw = rg + 8 * cc;
                int cbx = bq * 2 + i;
                float2 s0 = unpk2(acc2[cc][0][i]);
                float2 s1 = unpk2(acc2[cc][1][i]);
                float2 s2 = unpk2(acc2[cc][2][i]);
                float2 s3 = unpk2(acc2[cc][3][i]);
                redB[kw * (16*REDST) + jzw * REDST + cbx] =
                    make_float4(s0.x+s0.y, s1.x+s1.y, s2.x+s2.y, s3.x+s3.y);
            }
        bar_named(barid);                 // partials ready (subunit-wide)

        // ---- tail: lanes 0-15 of every warp: cell (batch=kw, col=lane) ----
        if (lane < 16) {
            float4 s = make_float4(0.f, 0.f, 0.f, 0.f);
            #pragma unroll
            for (int k = 0; k < 8; k++) {
                float4 q = redB[k * (16*REDST) + lane * REDST + kw];
                s.x += q.x; s.y += q.y; s.z += q.z; s.w += q.w;
            }
            float gi = fsig (s.x + xi);
            float gf = fsig (s.y + xf);
            float gg = ftanh(s.z + xg);
            float go = fsig (s.w + xo);
            float cn = gf * creg + gi * gg;
            creg = cn;
            float hn = go * ftanh(cn);

            if (t < TT - 1)
                g_hP[t & 1][(size_t)bglob * HH + jglob] = hn;
            else
                h_final[(size_t)bglob * HH + jglob] = hn;
            if (hs_out)
                hs_out[(size_t)t * BB * HH + (size_t)bglob * HH + jglob] = hn;
        }
        bar_named(barid);                 // h stores done; red safe to overwrite
        if (t < TT - 1 && lt == 0)
            st_release(&g_flags[fidx], base + (unsigned)t + 1u);
    }
}

// =================================================================================
// Host launch — 5 graph nodes
// =================================================================================
extern "C" void kernel_launch(void* const* d_in, const int* in_sizes, int n_in,
                              void* d_out, int out_size)
{
    (void)in_sizes; (void)n_in; (void)out_size;
    const float* inputs = (const float*)d_in[0];
    const float* W_ih1  = (const float*)d_in[1];
    const float* W_hh1  = (const float*)d_in[2];
    const float* b_ih1  = (const float*)d_in[3];
    const float* b_hh1  = (const float*)d_in[4];
    const float* W_ih2  = (const float*)d_in[5];
    const float* W_hh2  = (const float*)d_in[6];
    const float* b_ih2  = (const float*)d_in[7];
    const float* b_hh2  = (const float*)d_in[8];
    const float* W_lin  = (const float*)d_in[9];
    const float* b_lin  = (const float*)d_in[10];
    const float* h1_0   = (const float*)d_in[11];
    const float* c1_0   = (const float*)d_in[12];
    const float* h2_0   = (const float*)d_in[13];
    const float* c2_0   = (const float*)d_in[14];
    float* out = (float*)d_out;

    float *xp1, *xp2, *hA, *hs2;
    cudaGetSymbolAddress((void**)&xp1, g_xp1);
    cudaGetSymbolAddress((void**)&xp2, g_xp2);
    cudaGetSymbolAddress((void**)&hA,  g_hA);
    cudaGetSymbolAddress((void**)&hs2, g_hs2);

    cudaFuncSetAttribute(lstm_persist_kernel,
                         cudaFuncAttributeMaxDynamicSharedMemorySize,
                         STEP_SMEM_BYTES);

    // xp1 = inputs @ W_ih1^T + b_ih1 + b_hh1
    gemm_bias_kernel<<<dim3(G4/128, (TT*BB)/128), 256>>>(
        inputs, W_ih1, b_ih1, b_hh1, xp1, TT*BB, G4, II);

    // Layer 1: final h (batch-major) -> hA
    lstm_persist_kernel<<<NBLK, NTHR, STEP_SMEM_BYTES>>>(
        h1_0, c1_0, hA, W_hh1, xp1, (long long)BB * G4, nullptr);

    // xp2 = h1T @ W_ih2^T + b_ih2 + b_hh2
    gemm_bias_kernel<<<dim3(G4/128, 1), 256>>>(
        hA, W_ih2, b_ih2, b_hh2, xp2, BB, G4, HH);

    // Layer 2: hidden sequence streamed to hs2
    lstm_persist_kernel<<<NBLK, NTHR, STEP_SMEM_BYTES>>>(
        h2_0, c2_0, hA, W_hh2, xp2, 0LL, hs2);

    // out = hs2 @ W_lin^T + b_lin
    gemm_bias_kernel<<<dim3(OO/128, (TT*BB)/128), 256>>>(
        hs2, W_lin, b_lin, nullptr, out, TT*BB, OO, HH);
}

// round 14
// speedup vs baseline: 1.5713x; 1.5713x over previous
#include <cuda_runtime.h>
#include <math.h>
#include <stddef.h>

// Problem dims
#define TT 512
#define BB 64
#define II 256
#define HH 512
#define OO 256
#define G4 (4*HH)
#define NBLK 128
// 8 groups x 8 batches; block = 2 anti-phase subunits (groups 2p, 2p+1)
#define NGRP 8
#define UPG  32          // units per group (one per col-block)
#define BATG 8           // batches per group
#define NTHR 512

// ---------------- device scratch ----------------
__device__ float g_xp1[(size_t)TT*BB*G4];
__device__ float g_xp2[(size_t)BB*G4];
__device__ float g_hP[2][(size_t)BB*HH];    // ping-pong h, batch-major [b][col]
__device__ float g_hA[(size_t)BB*HH];       // layer-1 final h
__device__ float g_hs2[(size_t)TT*BB*HH];
__device__ unsigned g_flags[NGRP*UPG];      // per-unit monotonic step counters

// ---------------- helpers ----------------
typedef unsigned long long u64t;

__device__ __forceinline__ void fma2(u64t& acc, u64t a, u64t b) {
    asm volatile("fma.rn.f32x2 %0, %1, %2, %0;" : "+l"(acc) : "l"(a), "l"(b));
}
__device__ __forceinline__ u64t pk2(float x, float y) {
    u64t r; asm("mov.b64 %0, {%1, %2};" : "=l"(r) : "f"(x), "f"(y)); return r;
}
__device__ __forceinline__ float2 unpk2(u64t v) {
    float2 f; asm("mov.b64 {%0, %1}, %2;" : "=f"(f.x), "=f"(f.y) : "l"(v)); return f;
}
// L2-only 128-bit load (bypasses L1 — REQUIRED: other SMs rewrite these lines
// every 2 steps and L1 is not coherent).
__device__ __forceinline__ ulonglong2 ldg_cg2(const void* p) {
    ulonglong2 r;
    asm volatile("ld.global.cg.v2.u64 {%0, %1}, [%2];"
                 : "=l"(r.x), "=l"(r.y) : "l"(p));
    return r;
}
__device__ __forceinline__ void st_release(unsigned* p, unsigned v) {
    asm volatile("st.global.release.gpu.u32 [%0], %1;" :: "l"(p), "r"(v) : "memory");
}
__device__ __forceinline__ unsigned ld_acquire(const unsigned* p) {
    unsigned r;
    asm volatile("ld.global.acquire.gpu.u32 %0, [%1];" : "=r"(r) : "l"(p) : "memory");
    return r;
}
__device__ __forceinline__ void bar_named(int id) {
    asm volatile("bar.sync %0, 256;" :: "r"(id) : "memory");
}
__device__ __forceinline__ float fsig(float x)  { return __fdividef(1.f, 1.f + __expf(-x)); }
__device__ __forceinline__ float ftanh(float x) { return __fdividef(2.f, 1.f + __expf(-2.f*x)) - 1.f; }

// =================================================================================
// SGEMM with f32x2 (unchanged, passing)
// =================================================================================
__global__ __launch_bounds__(256) void gemm_bias_kernel(
    const float* __restrict__ A, const float* __restrict__ B,
    const float* __restrict__ bias1, const float* __restrict__ bias2,
    float* __restrict__ C, int M, int N, int K)
{
    __shared__ float As[8][128];
    __shared__ float Bs[8][128];

    const int tid  = threadIdx.x;
    const int row0 = blockIdx.y * 128;
    const int col0 = blockIdx.x * 128;

    const int lrow = tid >> 1;
    const int lcol = (tid & 1) << 2;
    const int tr   = (tid >> 4) << 3;
    const int tc   = (tid & 15) << 3;

    u64t acc2[4][8];
    #pragma unroll
    for (int i = 0; i < 4; i++)
        #pragma unroll
        for (int j = 0; j < 8; j++) acc2[i][j] = 0ull;

    for (int k0 = 0; k0 < K; k0 += 8) {
        float4 av = make_float4(0.f, 0.f, 0.f, 0.f);
        if (row0 + lrow < M)
            av = *(const float4*)(A + (size_t)(row0 + lrow) * K + k0 + lcol);
        As[lcol+0][lrow] = av.x;
        As[lcol+1][lrow] = av.y;
        As[lcol+2][lrow] = av.z;
        As[lcol+3][lrow] = av.w;

        float4 bv = *(const float4*)(B + (size_t)(col0 + lrow) * K + k0 + lcol);
        Bs[lcol+0][lrow] = bv.x;
        Bs[lcol+1][lrow] = bv.y;
        Bs[lcol+2][lrow] = bv.z;
        Bs[lcol+3][lrow] = bv.w;

        __syncthreads();

        #pragma unroll
        for (int kk = 0; kk < 8; kk++) {
            ulonglong2 raA = *(const ulonglong2*)&As[kk][tr];
            ulonglong2 raB = *(const ulonglong2*)&As[kk][tr + 4];
            float rb[8];
            *(float4*)(rb)     = *(const float4*)&Bs[kk][tc];
            *(float4*)(rb + 4) = *(const float4*)&Bs[kk][tc + 4];
            u64t rbd[8];
            #pragma unroll
            for (int j = 0; j < 8; j++) rbd[j] = pk2(rb[j], rb[j]);
            #pragma unroll
            for (int j = 0; j < 8; j++) {
                fma2(acc2[0][j], raA.x, rbd[j]);
                fma2(acc2[1][j], raA.y, rbd[j]);
                fma2(acc2[2][j], raB.x, rbd[j]);
                fma2(acc2[3][j], raB.y, rbd[j]);
            }
        }
        __syncthreads();
    }

    float bsum[8];
    #pragma unroll
    for (int j = 0; j < 8; j++) {
        float b = bias1 ? bias1[col0 + tc + j] : 0.f;
        if (bias2) b += bias2[col0 + tc + j];
        bsum[j] = b;
    }

    #pragma unroll
    for (int i2 = 0; i2 < 4; i2++) {
        #pragma unroll
        for (int half = 0; half < 2; half++) {
            int r = row0 + tr + i2 * 2 + half;
            if (r < M) {
                #pragma unroll
                for (int j = 0; j < 8; j += 4) {
                    float4 o;
                    float2 u0 = unpk2(acc2[i2][j+0]);
                    float2 u1 = unpk2(acc2[i2][j+1]);
                    float2 u2 = unpk2(acc2[i2][j+2]);
                    float2 u3 = unpk2(acc2[i2][j+3]);
                    o.x = (half ? u0.y : u0.x) + bsum[j+0];
                    o.y = (half ? u1.y : u1.x) + bsum[j+1];
                    o.z = (half ? u2.y : u2.x) + bsum[j+2];
                    o.w = (half ? u3.y : u3.x) + bsum[j+3];
                    *(float4*)(C + (size_t)r * N + col0 + tc + j) = o;
                }
            }
        }
    }
}

// =================================================================================
// Anti-phase dual-group persistent LSTM (R12 structure) with DIRECT-L2 h reads.
// Block b: cols [16*(b&31), +16) (64 gate rows); pair p=b>>5; subunit hh=tid>>8
// handles group 2p+hh (batches [8g, 8g+8)). Shared W 128KB in smem.
// Per step: centralized poll (lt<32, one flag each) -> bar -> compute with h
// loaded ld.global.cg straight from L2 (no staging, no wait_group, one less bar;
// 8-to-1 lane dedup keeps L2 traffic trivial; unroll-8 pipelines the latency
// under the 4-warp/SMSP FMA2 stream) -> partials bar -> tail -> bar -> release.
// Subunit layout: warp ks k-slice of 64; lane: rg=lane>>2 (cols rg,rg+8),
// bq=lane&3 (batches 2bq,2bq+1). Tail: lt<128, 1 cell (cb=lt>>4, jz=lt&15).
// =================================================================================
#define WS4F  (64*128)                   // W float4 (128KB)
#define REDST 9                          // red stride (float4) per col, padded
#define RED4F (8*16*REDST)               // red float4 per subunit (18KB)
#define STEP_SMEM_BYTES ((WS4F + 2*RED4F) * 16)   // 167,936 B

__global__ __launch_bounds__(NTHR, 1) void lstm_persist_kernel(
    const float* __restrict__ h0, const float* __restrict__ c0,
    float* __restrict__ h_final,
    const float* __restrict__ W, const float* __restrict__ xp,
    long long xp_t_stride, float* __restrict__ hs_out)
{
    extern __shared__ float smem[];
    float4* smem4 = (float4*)smem;
    __shared__ unsigned s_base[2];

    const int tid  = threadIdx.x;
    const int hh   = tid >> 8;            // subunit 0/1
    const int lt   = tid & 255;           // thread within subunit
    const int lane = tid & 31;
    const int ks   = (lt >> 5);           // k-slice 0..7 (64 k each)
    const int rg   = lane >> 2;           // col selector (cols rg, rg+8)
    const int bq   = lane & 3;            // batch pair selector (2bq, 2bq+1)
    const int p    = blockIdx.x >> 5;
    const int cb8  = blockIdx.x & 31;
    const int group = 2 * p + hh;
    const int jj0  = cb8 * 16;
    const int bq0  = group * BATG;
    const int fidx = group * UPG + cb8;
    const int barid = 1 + hh;

    float4* wS   = smem4;                            // [64 r][128 k4], swz k4^(col&7)
    float4* redB = smem4 + WS4F + hh * RED4F;        // [8 ks][16 col][9]

    // ---- stage shared W once: row r = col*4 + gate ----
    for (int idx = tid; idx < WS4F; idx += NTHR) {
        int r = idx >> 7, k4 = idx & 127;
        int col = r >> 2, g = r & 3;
        wS[r * 128 + (k4 ^ (col & 7))] =
            ((const float4*)(W + (size_t)(g * HH + jj0 + col) * HH))[k4];
    }

    // ---- tail cell state: lt<128: cb = lt>>4 (batch 0..7), jz = lt&15 (col) ----
    const int cb = lt >> 4, jz = lt & 15;
    const int bglob = bq0 + cb;
    const int jglob = jj0 + jz;
    float creg = 0.f;
    if (lt < 128) creg = c0[(size_t)bglob * HH + jglob];

    if (lt == 0) s_base[hh] = g_flags[fidx];
    __syncthreads();                      // only block-wide sync
    const unsigned base = s_base[hh];

    const int k4beg = ks * 16;

    for (int t = 0; t < TT; t++) {
        // ---- xp prefetch (consumed in tail) ----
        float xi = 0.f, xf = 0.f, xg = 0.f, xo = 0.f;
        if (lt < 128) {
            const float* xt = xp + (size_t)(xp_t_stride * t) + (size_t)bglob * G4 + jglob;
            xi = xt[0*HH];
            xf = xt[1*HH];
            xg = xt[2*HH];
            xo = xt[3*HH];
        }

        // ---- centralized poll: lt<32 threads, one unit flag each ----
        if (t > 0) {
            unsigned target = base + (unsigned)t;
            if (lt < UPG) {
                const unsigned* fp = &g_flags[group * UPG + lt];
                while ((int)(ld_acquire(fp) - target) < 0) { }
            }
            bar_named(barid);
        }

        // ---- compute: h DIRECT from L2; cols {rg,rg+8} x 4 gates x 2 b x 64 k ----
        const float* hsrc = (t == 0) ? h0 : g_hP[(t + 1) & 1];
        const float4* hp0 = (const float4*)hsrc + (size_t)(bq0 + bq * 2) * 128 + k4beg;
        const float4* hp1 = hp0 + 128;

        u64t acc2[2][4][2];
        #pragma unroll
        for (int cc = 0; cc < 2; cc++)
            #pragma unroll
            for (int g = 0; g < 4; g++)
                #pragma unroll
                for (int i = 0; i < 2; i++) acc2[cc][g][i] = 0ull;

        #pragma unroll 8
        for (int it = 0; it < 16; it++) {
            int k4g = k4beg + it;
            ulonglong2 hv0 = ldg_cg2(hp0 + it);
            ulonglong2 hv1 = ldg_cg2(hp1 + it);
            ulonglong2 wv[2][4];
            #pragma unroll
            for (int cc = 0; cc < 2; cc++)
                #pragma unroll
                for (int g = 0; g < 4; g++) {
                    int row = (rg + 8 * cc) * 4 + g;
                    wv[cc][g] = *(const ulonglong2*)(wS + row * 128 + (k4g ^ rg));
                }
            #pragma unroll
            for (int cc = 0; cc < 2; cc++)
                #pragma unroll
                for (int g = 0; g < 4; g++) {
                    fma2(acc2[cc][g][0], hv0.x, wv[cc][g].x);
                    fma2(acc2[cc][g][0], hv0.y, wv[cc][g].y);
                    fma2(acc2[cc][g][1], hv1.x, wv[cc][g].x);
                    fma2(acc2[cc][g][1], hv1.y, wv[cc][g].y);
                }
        }

        // ---- partials: redB[ks][col][batch] (stride 9), float4 over gates ----
        #pragma unroll
        for (int cc = 0; cc < 2; cc++)
            #pragma unroll
            for (int i = 0; i < 2; i++) {
                int jzw = rg + 8 * cc;
                int cbx = bq * 2 + i;
                float2 s0 = unpk2(acc2[cc][0][i]);
                float2 s1 = unpk2(acc2[cc][1][i]);
                float2 s2 = unpk2(acc2[cc][2][i]);
                float2 s3 = unpk2(acc2[cc][3][i]);
                redB[ks * (16*REDST) + jzw * REDST + cbx] =
                    make_float4(s0.x+s0.y, s1.x+s1.y, s2.x+s2.y, s3.x+s3.y);
            }
        bar_named(barid);                 // partials ready (subunit-wide)

        // ---- tail: one (batch, col) cell per thread, lt < 128 ----
        if (lt < 128) {
            float4 s = make_float4(0.f, 0.f, 0.f, 0.f);
            #pragma unroll
            for (int k = 0; k < 8; k++) {
                float4 q = redB[k * (16*REDST) + jz * REDST + cb];
                s.x += q.x; s.y += q.y; s.z += q.z; s.w += q.w;
            }
            float gi = fsig (s.x + xi);
            float gf = fsig (s.y + xf);
            float gg = ftanh(s.z + xg);
            float go = fsig (s.w + xo);
            float cn = gf * creg + gi * gg;
            creg = cn;
            float hn = go * ftanh(cn);

            if (t < TT - 1)
                g_hP[t & 1][(size_t)bglob * HH + jglob] = hn;
            else
                h_final[(size_t)bglob * HH + jglob] = hn;
            if (hs_out)
                hs_out[(size_t)t * BB * HH + (size_t)bglob * HH + jglob] = hn;
        }
        bar_named(barid);                 // h stores done; red safe to overwrite
        if (t < TT - 1 && lt == 0)
            st_release(&g_flags[fidx], base + (unsigned)t + 1u);
    }
}

// =================================================================================
// Host launch — 5 graph nodes
// =================================================================================
extern "C" void kernel_launch(void* const* d_in, const int* in_sizes, int n_in,
                              void* d_out, int out_size)
{
    (void)in_sizes; (void)n_in; (void)out_size;
    const float* inputs = (const float*)d_in[0];
    const float* W_ih1  = (const float*)d_in[1];
    const float* W_hh1  = (const float*)d_in[2];
    const float* b_ih1  = (const float*)d_in[3];
    const float* b_hh1  = (const float*)d_in[4];
    const float* W_ih2  = (const float*)d_in[5];
    const float* W_hh2  = (const float*)d_in[6];
    const float* b_ih2  = (const float*)d_in[7];
    const float* b_hh2  = (const float*)d_in[8];
    const float* W_lin  = (const float*)d_in[9];
    const float* b_lin  = (const float*)d_in[10];
    const float* h1_0   = (const float*)d_in[11];
    const float* c1_0   = (const float*)d_in[12];
    const float* h2_0   = (const float*)d_in[13];
    const float* c2_0   = (const float*)d_in[14];
    float* out = (float*)d_out;

    float *xp1, *xp2, *hA, *hs2;
    cudaGetSymbolAddress((void**)&xp1, g_xp1);
    cudaGetSymbolAddress((void**)&xp2, g_xp2);
    cudaGetSymbolAddress((void**)&hA,  g_hA);
    cudaGetSymbolAddress((void**)&hs2, g_hs2);

    cudaFuncSetAttribute(lstm_persist_kernel,
                         cudaFuncAttributeMaxDynamicSharedMemorySize,
                         STEP_SMEM_BYTES);

    // xp1 = inputs @ W_ih1^T + b_ih1 + b_hh1
    gemm_bias_kernel<<<dim3(G4/128, (TT*BB)/128), 256>>>(
        inputs, W_ih1, b_ih1, b_hh1, xp1, TT*BB, G4, II);

    // Layer 1: final h (batch-major) -> hA
    lstm_persist_kernel<<<NBLK, NTHR, STEP_SMEM_BYTES>>>(
        h1_0, c1_0, hA, W_hh1, xp1, (long long)BB * G4, nullptr);

    // xp2 = h1T @ W_ih2^T + b_ih2 + b_hh2
    gemm_bias_kernel<<<dim3(G4/128, 1), 256>>>(
        hA, W_ih2, b_ih2, b_hh2, xp2, BB, G4, HH);

    // Layer 2: hidden sequence streamed to hs2
    lstm_persist_kernel<<<NBLK, NTHR, STEP_SMEM_BYTES>>>(
        h2_0, c2_0, hA, W_hh2, xp2, 0LL, hs2);

    // out = hs2 @ W_lin^T + b_lin
    gemm_bias_kernel<<<dim3(OO/128, (TT*BB)/128), 256>>>(
        hs2, W_lin, b_lin, nullptr, out, TT*BB, OO, HH);
}

// round 15
// speedup vs baseline: 1.9478x; 1.2396x over previous
#include <cuda_runtime.h>
#include <math.h>
#include <stddef.h>

// Problem dims
#define TT 512
#define BB 64
#define II 256
#define HH 512
#define OO 256
#define G4 (4*HH)
#define NBLK 128
// 8 groups x 8 batches; block = 2 anti-phase subunits (groups 2p, 2p+1)
#define NGRP 8
#define UPG  32          // units per group (one per col-block)
#define BATG 8           // batches per group
#define NTHR 512

// ---------------- device scratch ----------------
__device__ float g_xp1[(size_t)TT*BB*G4];
__device__ float g_xp2[(size_t)BB*G4];
__device__ float g_hP[2][(size_t)BB*HH];    // ping-pong h, batch-major [b][col]
__device__ float g_hA[(size_t)BB*HH];       // layer-1 final h
__device__ float g_hs2[(size_t)TT*BB*HH];
__device__ unsigned g_flags[NGRP*UPG];      // per-unit monotonic step counters

// ---------------- helpers ----------------
typedef unsigned long long u64t;

__device__ __forceinline__ void fma2(u64t& acc, u64t a, u64t b) {
    asm volatile("fma.rn.f32x2 %0, %1, %2, %0;" : "+l"(acc) : "l"(a), "l"(b));
}
__device__ __forceinline__ u64t pk2(float x, float y) {
    u64t r; asm("mov.b64 %0, {%1, %2};" : "=l"(r) : "f"(x), "f"(y)); return r;
}
__device__ __forceinline__ float2 unpk2(u64t v) {
    float2 f; asm("mov.b64 {%0, %1}, %2;" : "=f"(f.x), "=f"(f.y) : "l"(v)); return f;
}
__device__ __forceinline__ void cp_async16(void* dst_smem, const void* src_gmem) {
    unsigned d = (unsigned)__cvta_generic_to_shared(dst_smem);
    asm volatile("cp.async.cg.shared.global [%0], [%1], 16;" :: "r"(d), "l"(src_gmem) : "memory");
}
__device__ __forceinline__ void st_release(unsigned* p, unsigned v) {
    asm volatile("st.global.release.gpu.u32 [%0], %1;" :: "l"(p), "r"(v) : "memory");
}
__device__ __forceinline__ unsigned ld_acquire(const unsigned* p) {
    unsigned r;
    asm volatile("ld.global.acquire.gpu.u32 %0, [%1];" : "=r"(r) : "l"(p) : "memory");
    return r;
}
__device__ __forceinline__ void bar_named(int id) {
    asm volatile("bar.sync %0, 256;" :: "r"(id) : "memory");
}
__device__ __forceinline__ float fsig(float x)  { return __fdividef(1.f, 1.f + __expf(-x)); }
__device__ __forceinline__ float ftanh(float x) { return __fdividef(2.f, 1.f + __expf(-2.f*x)) - 1.f; }

// =================================================================================
// SGEMM with f32x2 (unchanged, passing)
// =================================================================================
__global__ __launch_bounds__(256) void gemm_bias_kernel(
    const float* __restrict__ A, const float* __restrict__ B,
    const float* __restrict__ bias1, const float* __restrict__ bias2,
    float* __restrict__ C, int M, int N, int K)
{
    __shared__ float As[8][128];
    __shared__ float Bs[8][128];

    const int tid  = threadIdx.x;
    const int row0 = blockIdx.y * 128;
    const int col0 = blockIdx.x * 128;

    const int lrow = tid >> 1;
    const int lcol = (tid & 1) << 2;
    const int tr   = (tid >> 4) << 3;
    const int tc   = (tid & 15) << 3;

    u64t acc2[4][8];
    #pragma unroll
    for (int i = 0; i < 4; i++)
        #pragma unroll
        for (int j = 0; j < 8; j++) acc2[i][j] = 0ull;

    for (int k0 = 0; k0 < K; k0 += 8) {
        float4 av = make_float4(0.f, 0.f, 0.f, 0.f);
        if (row0 + lrow < M)
            av = *(const float4*)(A + (size_t)(row0 + lrow) * K + k0 + lcol);
        As[lcol+0][lrow] = av.x;
        As[lcol+1][lrow] = av.y;
        As[lcol+2][lrow] = av.z;
        As[lcol+3][lrow] = av.w;

        float4 bv = *(const float4*)(B + (size_t)(col0 + lrow) * K + k0 + lcol);
        Bs[lcol+0][lrow] = bv.x;
        Bs[lcol+1][lrow] = bv.y;
        Bs[lcol+2][lrow] = bv.z;
        Bs[lcol+3][lrow] = bv.w;

        __syncthreads();

        #pragma unroll
        for (int kk = 0; kk < 8; kk++) {
            ulonglong2 raA = *(const ulonglong2*)&As[kk][tr];
            ulonglong2 raB = *(const ulonglong2*)&As[kk][tr + 4];
            float rb[8];
            *(float4*)(rb)     = *(const float4*)&Bs[kk][tc];
            *(float4*)(rb + 4) = *(const float4*)&Bs[kk][tc + 4];
            u64t rbd[8];
            #pragma unroll
            for (int j = 0; j < 8; j++) rbd[j] = pk2(rb[j], rb[j]);
            #pragma unroll
            for (int j = 0; j < 8; j++) {
                fma2(acc2[0][j], raA.x, rbd[j]);
                fma2(acc2[1][j], raA.y, rbd[j]);
                fma2(acc2[2][j], raB.x, rbd[j]);
                fma2(acc2[3][j], raB.y, rbd[j]);
            }
        }
        __syncthreads();
    }

    float bsum[8];
    #pragma unroll
    for (int j = 0; j < 8; j++) {
        float b = bias1 ? bias1[col0 + tc + j] : 0.f;
        if (bias2) b += bias2[col0 + tc + j];
        bsum[j] = b;
    }

    #pragma unroll
    for (int i2 = 0; i2 < 4; i2++) {
        #pragma unroll
        for (int half = 0; half < 2; half++) {
            int r = row0 + tr + i2 * 2 + half;
            if (r < M) {
                #pragma unroll
                for (int j = 0; j < 8; j += 4) {
                    float4 o;
                    float2 u0 = unpk2(acc2[i2][j+0]);
                    float2 u1 = unpk2(acc2[i2][j+1]);
                    float2 u2 = unpk2(acc2[i2][j+2]);
                    float2 u3 = unpk2(acc2[i2][j+3]);
                    o.x = (half ? u0.y : u0.x) + bsum[j+0];
                    o.y = (half ? u1.y : u1.x) + bsum[j+1];
                    o.z = (half ? u2.y : u2.x) + bsum[j+2];
                    o.w = (half ? u3.y : u3.x) + bsum[j+3];
                    *(float4*)(C + (size_t)r * N + col0 + tc + j) = o;
                }
            }
        }
    }
}

// =================================================================================
// Anti-phase dual-group persistent LSTM (R12 skeleton) + per-warp self-staging.
// Block b: cols [16*(b&31), +16) (64 gate rows); pair p=b>>5; subunit hh=tid>>8
// handles group 2p+hh (batches [8g, 8g+8)). Shared W 128KB in smem.
//
// Per step:
//   1. centralized poll: lt<32 threads each watch ONE unit flag -> bar (R12)
//   2. per-warp stage: warp kw cp.asyncs ONLY its own 2KB k-slice, wait_group 0
//      + syncwarp (NO block bar -- warps proceed to compute independently)
//   3. compute own k-slice (f32x2, 2 cols x 4 gates x 2 batches x 64 k / thread)
//   4. partials -> smem; bar
//   5. tail (lt<128, 1 cell); bar; release (lt==0)
// 3 bars/step (R12 had 4); staging LSU traffic halved vs R12.
// =================================================================================
#define WS4F  (64*128)                   // W float4 (128KB)
#define HS4F  (8*128)                    // h float4 per subunit: 8 warps x 128 (16KB)
#define REDST 9                          // red stride (float4) per col, padded
#define RED4F (8*16*REDST)               // red float4 per subunit (18KB)
#define STEP_SMEM_BYTES ((WS4F + 2*HS4F + 2*RED4F) * 16)   // 200,704 B

__global__ __launch_bounds__(NTHR, 1) void lstm_persist_kernel(
    const float* __restrict__ h0, const float* __restrict__ c0,
    float* __restrict__ h_final,
    const float* __restrict__ W, const float* __restrict__ xp,
    long long xp_t_stride, float* __restrict__ hs_out)
{
    extern __shared__ float smem[];
    float4* smem4 = (float4*)smem;
    __shared__ unsigned s_base[2];

    const int tid  = threadIdx.x;
    const int hh   = tid >> 8;            // subunit 0/1
    const int lt   = tid & 255;           // thread within subunit
    const int lane = tid & 31;
    const int kw   = lt >> 5;             // warp in subunit = k-slice 0..7
    const int rg   = lane >> 2;           // col selector (cols rg, rg+8)
    const int bq   = lane & 3;            // batch pair selector (2bq, 2bq+1)
    const int p    = blockIdx.x >> 5;
    const int cb8  = blockIdx.x & 31;
    const int group = 2 * p + hh;
    const int jj0  = cb8 * 16;
    const int bq0  = group * BATG;
    const int fidx = group * UPG + cb8;
    const int barid = 1 + hh;

    float4* wS   = smem4;                               // [64 r][128 k4], swz k4^(col&7)
    float4* hS   = smem4 + WS4F + hh * HS4F;            // [kw][b][16 k4], swz k4l^(b&7)
    float4* redB = smem4 + WS4F + 2*HS4F + hh * RED4F;  // [8 kw][16 col][9]

    // ---- stage shared W once: row r = col*4 + gate ----
    for (int idx = tid; idx < WS4F; idx += NTHR) {
        int r = idx >> 7, k4 = idx & 127;
        int col = r >> 2, g = r & 3;
        wS[r * 128 + (k4 ^ (col & 7))] =
            ((const float4*)(W + (size_t)(g * HH + jj0 + col) * HH))[k4];
    }

    // ---- tail cell state: lt<128: cb = lt>>4 (batch 0..7), jz = lt&15 (col) ----
    const int cb = lt >> 4, jz = lt & 15;
    const int bglob = bq0 + cb;
    const int jglob = jj0 + jz;
    float creg = 0.f;
    if (lt < 128) creg = c0[(size_t)bglob * HH + jglob];

    if (lt == 0) s_base[hh] = g_flags[fidx];
    __syncthreads();                      // only block-wide sync
    const unsigned base = s_base[hh];

    float4* hW = hS + kw * 128;           // this warp's slice [8 b][16 k4]

    for (int t = 0; t < TT; t++) {
        // ---- xp prefetch (consumed in tail) ----
        float xi = 0.f, xf = 0.f, xg = 0.f, xo = 0.f;
        if (lt < 128) {
            const float* xt = xp + (size_t)(xp_t_stride * t) + (size_t)bglob * G4 + jglob;
            xi = xt[0*HH];
            xf = xt[1*HH];
            xg = xt[2*HH];
            xo = xt[3*HH];
        }

        // ---- centralized poll: lt<32 threads, one unit flag each -> bar ----
        if (t > 0) {
            unsigned target = base + (unsigned)t;
            if (lt < UPG) {
                const unsigned* fp = &g_flags[group * UPG + lt];
                while ((int)(ld_acquire(fp) - target) < 0) { }
            }
            bar_named(barid);
        }

        // ---- per-warp stage: own 2KB slice, no block bar ----
        const float* hsrc = (t == 0) ? h0 : g_hP[(t + 1) & 1];
        #pragma unroll
        for (int q = 0; q < 4; q++) {
            int idx = lane * 4 + q;       // 0..127
            int b   = idx >> 4;
            int k4l = idx & 15;
            cp_async16(hW + b * 16 + (k4l ^ (b & 7)),
                       (const float4*)hsrc + (size_t)(bq0 + b) * 128 + kw * 16 + k4l);
        }
        asm volatile("cp.async.commit_group;" ::: "memory");
        asm volatile("cp.async.wait_group 0;" ::: "memory");
        __syncwarp();

        // ---- compute own k-slice: cols {rg,rg+8} x 4 gates x 2 batches x 64 k ----
        u64t acc2[2][4][2];
        #pragma unroll
        for (int cc = 0; cc < 2; cc++)
            #pragma unroll
            for (int g = 0; g < 4; g++)
                #pragma unroll
                for (int i = 0; i < 2; i++) acc2[cc][g][i] = 0ull;

        #pragma unroll 8
        for (int it = 0; it < 16; it++) {
            int k4g = kw * 16 + it;
            ulonglong2 wv[2][4];
            #pragma unroll
            for (int cc = 0; cc < 2; cc++)
                #pragma unroll
                for (int g = 0; g < 4; g++) {
                    int row = (rg + 8 * cc) * 4 + g;
                    wv[cc][g] = *(const ulonglong2*)(wS + row * 128 + (k4g ^ rg));
                }
            ulonglong2 hv[2];
            #pragma unroll
            for (int i = 0; i < 2; i++) {
                int b = bq * 2 + i;
                hv[i] = *(const ulonglong2*)(hW + b * 16 + (it ^ (b & 7)));
            }
            #pragma unroll
            for (int cc = 0; cc < 2; cc++)
                #pragma unroll
                for (int g = 0; g < 4; g++)
                    #pragma unroll
                    for (int i = 0; i < 2; i++) {
                        fma2(acc2[cc][g][i], hv[i].x, wv[cc][g].x);
                        fma2(acc2[cc][g][i], hv[i].y, wv[cc][g].y);
                    }
        }

        // ---- partials: redB[kw][col][batch] (stride 9), float4 over gates ----
        #pragma unroll
        for (int cc = 0; cc < 2; cc++)
            #pragma unroll
            for (int i = 0; i < 2; i++) {
                int jzw = rg + 8 * cc;
                int cbx = bq * 2 + i;
                float2 s0 = unpk2(acc2[cc][0][i]);
                float2 s1 = unpk2(acc2[cc][1][i]);
                float2 s2 = unpk2(acc2[cc][2][i]);
                float2 s3 = unpk2(acc2[cc][3][i]);
                redB[kw * (16*REDST) + jzw * REDST + cbx] =
                    make_float4(s0.x+s0.y, s1.x+s1.y, s2.x+s2.y, s3.x+s3.y);
            }
        bar_named(barid);                 // partials ready (subunit-wide)

        // ---- tail: one (batch, col) cell per thread, lt < 128 ----
        if (lt < 128) {
            float4 s = make_float4(0.f, 0.f, 0.f, 0.f);
            #pragma unroll
            for (int k = 0; k < 8; k++) {
                float4 q = redB[k * (16*REDST) + jz * REDST + cb];
                s.x += q.x; s.y += q.y; s.z += q.z; s.w += q.w;
            }
            float gi = fsig (s.x + xi);
            float gf = fsig (s.y + xf);
            float gg = ftanh(s.z + xg);
            float go = fsig (s.w + xo);
            float cn = gf * creg + gi * gg;
            creg = cn;
            float hn = go * ftanh(cn);

            if (t < TT - 1)
                g_hP[t & 1][(size_t)bglob * HH + jglob] = hn;
            else
                h_final[(size_t)bglob * HH + jglob] = hn;
            if (hs_out)
                hs_out[(size_t)t * BB * HH + (size_t)bglob * HH + jglob] = hn;
        }
        bar_named(barid);                 // h stores done; red/hS safe to overwrite
        if (t < TT - 1 && lt == 0)
            st_release(&g_flags[fidx], base + (unsigned)t + 1u);
    }
}

// =================================================================================
// Host launch — 5 graph nodes
// =================================================================================
extern "C" void kernel_launch(void* const* d_in, const int* in_sizes, int n_in,
                              void* d_out, int out_size)
{
    (void)in_sizes; (void)n_in; (void)out_size;
    const float* inputs = (const float*)d_in[0];
    const float* W_ih1  = (const float*)d_in[1];
    const float* W_hh1  = (const float*)d_in[2];
    const float* b_ih1  = (const float*)d_in[3];
    const float* b_hh1  = (const float*)d_in[4];
    const float* W_ih2  = (const float*)d_in[5];
    const float* W_hh2  = (const float*)d_in[6];
    const float* b_ih2  = (const float*)d_in[7];
    const float* b_hh2  = (const float*)d_in[8];
    const float* W_lin  = (const float*)d_in[9];
    const float* b_lin  = (const float*)d_in[10];
    const float* h1_0   = (const float*)d_in[11];
    const float* c1_0   = (const float*)d_in[12];
    const float* h2_0   = (const float*)d_in[13];
    const float* c2_0   = (const float*)d_in[14];
    float* out = (float*)d_out;

    float *xp1, *xp2, *hA, *hs2;
    cudaGetSymbolAddress((void**)&xp1, g_xp1);
    cudaGetSymbolAddress((void**)&xp2, g_xp2);
    cudaGetSymbolAddress((void**)&hA,  g_hA);
    cudaGetSymbolAddress((void**)&hs2, g_hs2);

    cudaFuncSetAttribute(lstm_persist_kernel,
                         cudaFuncAttributeMaxDynamicSharedMemorySize,
                         STEP_SMEM_BYTES);

    // xp1 = inputs @ W_ih1^T + b_ih1 + b_hh1
    gemm_bias_kernel<<<dim3(G4/128, (TT*BB)/128), 256>>>(
        inputs, W_ih1, b_ih1, b_hh1, xp1, TT*BB, G4, II);

    // Layer 1: final h (batch-major) -> hA
    lstm_persist_kernel<<<NBLK, NTHR, STEP_SMEM_BYTES>>>(
        h1_0, c1_0, hA, W_hh1, xp1, (long long)BB * G4, nullptr);

    // xp2 = h1T @ W_ih2^T + b_ih2 + b_hh2
    gemm_bias_kernel<<<dim3(G4/128, 1), 256>>>(
        hA, W_ih2, b_ih2, b_hh2, xp2, BB, G4, HH);

    // Layer 2: hidden sequence streamed to hs2
    lstm_persist_kernel<<<NBLK, NTHR, STEP_SMEM_BYTES>>>(
        h2_0, c2_0, hA, W_hh2, xp2, 0LL, hs2);

    // out = hs2 @ W_lin^T + b_lin
    gemm_bias_kernel<<<dim3(OO/128, (TT*BB)/128), 256>>>(
        hs2, W_lin, b_lin, nullptr, out, TT*BB, OO, HH);
}

// round 16
// speedup vs baseline: 2.5709x; 1.3199x over previous
#include <cuda_runtime.h>
#include <math.h>
#include <stddef.h>

// Problem dims
#define TT 512
#define BB 64
#define II 256
#define HH 512
#define OO 256
#define G4 (4*HH)
#define NBLK 128
// 8 groups x 8 batches; block = 2 anti-phase subunits (groups 2p, 2p+1)
#define NGRP 8
#define UPG  32          // units per group (one per col-block)
#define BATG 8           // batches per group
#define NTHR 512

// ---------------- device scratch ----------------
__device__ float g_xp1[(size_t)TT*BB*G4];
__device__ float g_xp2[(size_t)BB*G4];
__device__ float g_hP[2][(size_t)BB*HH];    // ping-pong h, batch-major [b][col]
__device__ float g_hA[(size_t)BB*HH];       // layer-1 final h
__device__ float g_hs2[(size_t)TT*BB*HH];
__device__ unsigned g_flags[NGRP*UPG];      // per-unit step counters (base bookkeeping)
__device__ unsigned g_cnt[NGRP];            // per-group release counters (32 per step)

// ---------------- helpers ----------------
typedef unsigned long long u64t;

__device__ __forceinline__ void fma2(u64t& acc, u64t a, u64t b) {
    asm volatile("fma.rn.f32x2 %0, %1, %2, %0;" : "+l"(acc) : "l"(a), "l"(b));
}
__device__ __forceinline__ u64t pk2(float x, float y) {
    u64t r; asm("mov.b64 %0, {%1, %2};" : "=l"(r) : "f"(x), "f"(y)); return r;
}
__device__ __forceinline__ float2 unpk2(u64t v) {
    float2 f; asm("mov.b64 {%0, %1}, %2;" : "=f"(f.x), "=f"(f.y) : "l"(v)); return f;
}
__device__ __forceinline__ void cp_async16(void* dst_smem, const void* src_gmem) {
    unsigned d = (unsigned)__cvta_generic_to_shared(dst_smem);
    asm volatile("cp.async.cg.shared.global [%0], [%1], 16;" :: "r"(d), "l"(src_gmem) : "memory");
}
__device__ __forceinline__ void red_add_release(unsigned* p, unsigned v) {
    asm volatile("red.global.release.gpu.add.u32 [%0], %1;" :: "l"(p), "r"(v) : "memory");
}
__device__ __forceinline__ unsigned ld_acquire(const unsigned* p) {
    unsigned r;
    asm volatile("ld.global.acquire.gpu.u32 %0, [%1];" : "=r"(r) : "l"(p) : "memory");
    return r;
}
__device__ __forceinline__ void bar_named(int id, int cnt) {
    asm volatile("bar.sync %0, %1;" :: "r"(id), "r"(cnt) : "memory");
}
__device__ __forceinline__ float fsig(float x)  { return __fdividef(1.f, 1.f + __expf(-x)); }
__device__ __forceinline__ float ftanh(float x) { return __fdividef(2.f, 1.f + __expf(-2.f*x)) - 1.f; }

// =================================================================================
// SGEMM with f32x2 + register/smem double buffering (1 sync per k-tile).
// C[M,N] = A[M,K] * B[N,K]^T + bias1[N] (+ bias2[N])
// =================================================================================
__global__ __launch_bounds__(256) void gemm_bias_kernel(
    const float* __restrict__ A, const float* __restrict__ B,
    const float* __restrict__ bias1, const float* __restrict__ bias2,
    float* __restrict__ C, int M, int N, int K)
{
    __shared__ float As[2][8][128];
    __shared__ float Bs[2][8][128];

    const int tid  = threadIdx.x;
    const int row0 = blockIdx.y * 128;
    const int col0 = blockIdx.x * 128;

    const int lrow = tid >> 1;
    const int lcol = (tid & 1) << 2;
    const int tr   = (tid >> 4) << 3;
    const int tc   = (tid & 15) << 3;
    const int KT   = K >> 3;

    u64t acc2[4][8];
    #pragma unroll
    for (int i = 0; i < 4; i++)
        #pragma unroll
        for (int j = 0; j < 8; j++) acc2[i][j] = 0ull;

    // gmem loaders
    auto ldA = [&](int kt) {
        float4 v = make_float4(0.f, 0.f, 0.f, 0.f);
        if (row0 + lrow < M)
            v = *(const float4*)(A + (size_t)(row0 + lrow) * K + kt * 8 + lcol);
        return v;
    };
    auto ldB = [&](int kt) {
        return *(const float4*)(B + (size_t)(col0 + lrow) * K + kt * 8 + lcol);
    };
    auto sts = [&](int buf, float4 av, float4 bv) {
        As[buf][lcol+0][lrow] = av.x;
        As[buf][lcol+1][lrow] = av.y;
        As[buf][lcol+2][lrow] = av.z;
        As[buf][lcol+3][lrow] = av.w;
        Bs[buf][lcol+0][lrow] = bv.x;
        Bs[buf][lcol+1][lrow] = bv.y;
        Bs[buf][lcol+2][lrow] = bv.z;
        Bs[buf][lcol+3][lrow] = bv.w;
    };

    // prologue: tile 0 -> buf 0; tile 1 -> regs
    float4 an = make_float4(0,0,0,0), bn = make_float4(0,0,0,0);
    {
        float4 a0 = ldA(0), b0 = ldB(0);
        sts(0, a0, b0);
        if (KT > 1) { an = ldA(1); bn = ldB(1); }
    }
    __syncthreads();

    for (int kt = 0; kt < KT; kt++) {
        if (kt + 1 < KT) sts((kt + 1) & 1, an, bn);       // fill other buf
        if (kt + 2 < KT) { an = ldA(kt + 2); bn = ldB(kt + 2); } // prefetch

        const float (*Ac)[128] = As[kt & 1];
        const float (*Bc)[128] = Bs[kt & 1];
        #pragma unroll
        for (int kk = 0; kk < 8; kk++) {
            ulonglong2 raA = *(const ulonglong2*)&Ac[kk][tr];
            ulonglong2 raB = *(const ulonglong2*)&Ac[kk][tr + 4];
            float rb[8];
            *(float4*)(rb)     = *(const float4*)&Bc[kk][tc];
            *(float4*)(rb + 4) = *(const float4*)&Bc[kk][tc + 4];
            u64t rbd[8];
            #pragma unroll
            for (int j = 0; j < 8; j++) rbd[j] = pk2(rb[j], rb[j]);
            #pragma unroll
            for (int j = 0; j < 8; j++) {
                fma2(acc2[0][j], raA.x, rbd[j]);
                fma2(acc2[1][j], raA.y, rbd[j]);
                fma2(acc2[2][j], raB.x, rbd[j]);
                fma2(acc2[3][j], raB.y, rbd[j]);
            }
        }
        __syncthreads();
    }

    float bsum[8];
    #pragma unroll
    for (int j = 0; j < 8; j++) {
        float b = bias1 ? bias1[col0 + tc + j] : 0.f;
        if (bias2) b += bias2[col0 + tc + j];
        bsum[j] = b;
    }

    #pragma unroll
    for (int i2 = 0; i2 < 4; i2++) {
        #pragma unroll
        for (int half = 0; half < 2; half++) {
            int r = row0 + tr + i2 * 2 + half;
            if (r < M) {
                #pragma unroll
                for (int j = 0; j < 8; j += 4) {
                    float4 o;
                    float2 u0 = unpk2(acc2[i2][j+0]);
                    float2 u1 = unpk2(acc2[i2][j+1]);
                    float2 u2 = unpk2(acc2[i2][j+2]);
                    float2 u3 = unpk2(acc2[i2][j+3]);
                    o.x = (half ? u0.y : u0.x) + bsum[j+0];
                    o.y = (half ? u1.y : u1.x) + bsum[j+1];
                    o.z = (half ? u2.y : u2.x) + bsum[j+2];
                    o.w = (half ? u3.y : u3.x) + bsum[j+3];
                    *(float4*)(C + (size_t)r * N + col0 + tc + j) = o;
                }
            }
        }
    }
}

// =================================================================================
// Anti-phase dual-group persistent LSTM (R12 skeleton) with:
//  - group release COUNTER (red.release.add) instead of 32 flags; single-line poll
//  - poll for h(t+1) overlapped with the tail of step t (warp-4 poller): at loop
//    entry h(t) is already certified, so staging starts immediately
//  - hs_out stores moved after the release (off the inter-unit critical path)
// Everything else (stage, compute, partials, tail, swizzles) is byte-identical R12.
// =================================================================================
#define WS4F  (64*128)                   // W float4 (128KB)
#define HS4F  (BATG*128)                 // h float4 per subunit (16KB)
#define REDST 9                          // red stride (float4) per col, padded
#define RED4F (8*16*REDST)               // red float4 per subunit (18KB)
#define STEP_SMEM_BYTES ((WS4F + 2*HS4F + 2*RED4F) * 16)   // 200,704 B

__global__ __launch_bounds__(NTHR, 1) void lstm_persist_kernel(
    const float* __restrict__ h0, const float* __restrict__ c0,
    float* __restrict__ h_final,
    const float* __restrict__ W, const float* __restrict__ xp,
    long long xp_t_stride, float* __restrict__ hs_out)
{
    extern __shared__ float smem[];
    float4* smem4 = (float4*)smem;
    __shared__ unsigned s_base[2];

    const int tid  = threadIdx.x;
    const int hh   = tid >> 8;            // subunit 0/1
    const int lt   = tid & 255;           // thread within subunit
    const int lane = tid & 31;
    const int ks   = (lt >> 5);           // k-slice 0..7 (64 k each)
    const int rg   = lane >> 2;           // col selector (cols rg, rg+8)
    const int bq   = lane & 3;            // batch pair selector (2bq, 2bq+1)
    const int p    = blockIdx.x >> 5;
    const int cb8  = blockIdx.x & 31;
    const int group = 2 * p + hh;
    const int jj0  = cb8 * 16;
    const int bq0  = group * BATG;
    const int fidx = group * UPG + cb8;
    const int barA = 1 + hh;              // subunit-wide (256)
    const int barD = 3 + hh;              // tail-only (128)

    float4* wS   = smem4;                            // [64 r][128 k4], swz k4^(col&7)
    float4* hS   = smem4 + WS4F + hh * HS4F;         // [8 b][128 k4], swz k4^b
    float4* redB = smem4 + WS4F + 2*HS4F + hh * RED4F; // [8 ks][16 col][9]

    // ---- stage shared W once: row r = col*4 + gate ----
    for (int idx = tid; idx < WS4F; idx += NTHR) {
        int r = idx >> 7, k4 = idx & 127;
        int col = r >> 2, g = r & 3;
        wS[r * 128 + (k4 ^ (col & 7))] =
            ((const float4*)(W + (size_t)(g * HH + jj0 + col) * HH))[k4];
    }

    // ---- tail cell state: lt<128: cb = lt>>4 (batch 0..7), jz = lt&15 (col) ----
    const int cb = lt >> 4, jz = lt & 15;
    const int bglob = bq0 + cb;
    const int jglob = jj0 + jz;
    float creg = 0.f;
    if (lt < 128) creg = c0[(size_t)bglob * HH + jglob];

    if (lt == 0) s_base[hh] = g_flags[fidx];   // own flag: safe base read
    __syncthreads();                           // only block-wide sync
    const unsigned base = s_base[hh];

    const int k4beg = ks * 16;

    for (int t = 0; t < TT; t++) {
        // h(t) is certified ready at loop entry (poll done during previous tail)

        // ---- xp prefetch (consumed in tail; long slack) ----
        float xi = 0.f, xf = 0.f, xg = 0.f, xo = 0.f;
        if (lt < 128) {
            const float* xt = xp + (size_t)(xp_t_stride * t) + (size_t)bglob * G4 + jglob;
            xi = xt[0*HH];
            xf = xt[1*HH];
            xg = xt[2*HH];
            xo = xt[3*HH];
        }

        // ---- stage own group's h slice (16KB), block-subunit-wide (R12) ----
        const float* hsrc = (t == 0) ? h0 : g_hP[(t + 1) & 1];
        for (int idx = lt; idx < HS4F; idx += 256) {
            int bl = idx >> 7, k4 = idx & 127;
            cp_async16(hS + bl * 128 + (k4 ^ bl),
                       (const float4*)hsrc + (size_t)(bq0 + bl) * 128 + k4);
        }
        asm volatile("cp.async.commit_group;" ::: "memory");
        asm volatile("cp.async.wait_group 0;" ::: "memory");
        bar_named(barA, 256);

        // ---- compute: cols {rg,rg+8} x 4 gates x 2 batches x 64 k (R12) ----
        u64t acc2[2][4][2];
        #pragma unroll
        for (int cc = 0; cc < 2; cc++)
            #pragma unroll
            for (int g = 0; g < 4; g++)
                #pragma unroll
                for (int i = 0; i < 2; i++) acc2[cc][g][i] = 0ull;

        #pragma unroll 8
        for (int it = 0; it < 16; it++) {
            int k4g = k4beg + it;
            ulonglong2 wv[2][4];
            #pragma unroll
            for (int cc = 0; cc < 2; cc++)
                #pragma unroll
                for (int g = 0; g < 4; g++) {
                    int row = (rg + 8 * cc) * 4 + g;
                    wv[cc][g] = *(const ulonglong2*)(wS + row * 128 + (k4g ^ rg));
                }
            ulonglong2 hv[2];
            #pragma unroll
            for (int i = 0; i < 2; i++) {
                int b = bq * 2 + i;
                hv[i] = *(const ulonglong2*)(hS + b * 128 + (k4g ^ b));
            }
            #pragma unroll
            for (int cc = 0; cc < 2; cc++)
                #pragma unroll
                for (int g = 0; g < 4; g++)
                    #pragma unroll
                    for (int i = 0; i < 2; i++) {
                        fma2(acc2[cc][g][i], hv[i].x, wv[cc][g].x);
                        fma2(acc2[cc][g][i], hv[i].y, wv[cc][g].y);
                    }
        }

        // ---- partials: redB[ks][col][batch] (stride 9), float4 over gates ----
        #pragma unroll
        for (int cc = 0; cc < 2; cc++)
            #pragma unroll
            for (int i = 0; i < 2; i++) {
                int jzw = rg + 8 * cc;
                int cbx = bq * 2 + i;
                float2 s0 = unpk2(acc2[cc][0][i]);
                float2 s1 = unpk2(acc2[cc][1][i]);
                float2 s2 = unpk2(acc2[cc][2][i]);
                float2 s3 = unpk2(acc2[cc][3][i]);
                redB[ks * (16*REDST) + jzw * REDST + cbx] =
                    make_float4(s0.x+s0.y, s1.x+s1.y, s2.x+s2.y, s3.x+s3.y);
            }
        bar_named(barA, 256);             // partials ready (subunit-wide)

        // ---- tail (warps 0-3) || poll for h(t+1) (warp 4, lane 0) ----
        if (lt < 128) {
            float4 s = make_float4(0.f, 0.f, 0.f, 0.f);
            #pragma unroll
            for (int k = 0; k < 8; k++) {
                float4 q = redB[k * (16*REDST) + jz * REDST + cb];
                s.x += q.x; s.y += q.y; s.z += q.z; s.w += q.w;
            }
            float gi = fsig (s.x + xi);
            float gf = fsig (s.y + xf);
            float gg = ftanh(s.z + xg);
            float go = fsig (s.w + xo);
            float cn = gf * creg + gi * gg;
            creg = cn;
            float hn = go * ftanh(cn);

            if (t < TT - 1) {
                g_hP[t & 1][(size_t)bglob * HH + jglob] = hn;
                bar_named(barD, 128);     // tail h stores done
                if (lt == 0) {
                    g_flags[fidx] = base + (unsigned)t + 1u;    // base bookkeeping
                    red_add_release(&g_cnt[group], 1u);          // fire-and-forget
                }
            } else {
                h_final[(size_t)bglob * HH + jglob] = hn;
            }
            if (hs_out)                    // off the inter-unit critical path
                hs_out[(size_t)t * BB * HH + (size_t)bglob * HH + jglob] = hn;
        } else if (lt == 128 && t < TT - 1) {
            // poll group counter for h(t+1): 32 releases per step
            unsigned target = 32u * (base + (unsigned)t + 1u);
            const unsigned* cp = &g_cnt[group];
            while ((int)(ld_acquire(cp) - target) < 0) { }
        }
        bar_named(barA, 256);             // join tail + poller; h(t+1) certified
    }
}

// =================================================================================
// Host launch — 5 graph nodes
// =================================================================================
extern "C" void kernel_launch(void* const* d_in, const int* in_sizes, int n_in,
                              void* d_out, int out_size)
{
    (void)in_sizes; (void)n_in; (void)out_size;
    const float* inputs = (const float*)d_in[0];
    const float* W_ih1  = (const float*)d_in[1];
    const float* W_hh1  = (const float*)d_in[2];
    const float* b_ih1  = (const float*)d_in[3];
    const float* b_hh1  = (const float*)d_in[4];
    const float* W_ih2  = (const float*)d_in[5];
    const float* W_hh2  = (const float*)d_in[6];
    const float* b_ih2  = (const float*)d_in[7];
    const float* b_hh2  = (const float*)d_in[8];
    const float* W_lin  = (const float*)d_in[9];
    const float* b_lin  = (const float*)d_in[10];
    const float* h1_0   = (const float*)d_in[11];
    const float* c1_0   = (const float*)d_in[12];
    const float* h2_0   = (const float*)d_in[13];
    const float* c2_0   = (const float*)d_in[14];
    float* out = (float*)d_out;

    float *xp1, *xp2, *hA, *hs2;
    cudaGetSymbolAddress((void**)&xp1, g_xp1);
    cudaGetSymbolAddress((void**)&xp2, g_xp2);
    cudaGetSymbolAddress((void**)&hA,  g_hA);
    cudaGetSymbolAddress((void**)&hs2, g_hs2);

    cudaFuncSetAttribute(lstm_persist_kernel,
                         cudaFuncAttributeMaxDynamicSharedMemorySize,
                         STEP_SMEM_BYTES);

    // xp1 = inputs @ W_ih1^T + b_ih1 + b_hh1
    gemm_bias_kernel<<<dim3(G4/128, (TT*BB)/128), 256>>>(
        inputs, W_ih1, b_ih1, b_hh1, xp1, TT*BB, G4, II);

    // Layer 1: final h (batch-major) -> hA
    lstm_persist_kernel<<<NBLK, NTHR, STEP_SMEM_BYTES>>>(
        h1_0, c1_0, hA, W_hh1, xp1, (long long)BB * G4, nullptr);

    // xp2 = h1T @ W_ih2^T + b_ih2 + b_hh2
    gemm_bias_kernel<<<dim3(G4/128, 1), 256>>>(
        hA, W_ih2, b_ih2, b_hh2, xp2, BB, G4, HH);

    // Layer 2: hidden sequence streamed to hs2
    lstm_persist_kernel<<<NBLK, NTHR, STEP_SMEM_BYTES>>>(
        h2_0, c2_0, hA, W_hh2, xp2, 0LL, hs2);

    // out = hs2 @ W_lin^T + b_lin
    gemm_bias_kernel<<<dim3(OO/128, (TT*BB)/128), 256>>>(
        hs2, W_lin, b_lin, nullptr, out, TT*BB, OO, HH);
}